// round 12
// baseline (speedup 1.0000x reference)
#include <cuda_runtime.h>
#include <cuda_fp16.h>
#include <cstdint>

// Problem constants
#define BB   64
#define NN   4096
#define EE   4096
#define NNZ  32768
#define CC   256

// ---------------- static device scratch (no allocs allowed) ----------------
__device__ __half g_ahf[(size_t)BB * NN * CC];     // 134 MB (X_h / Z1)
__device__ __half g_ehf[(size_t)BB * EE * CC];     // 134 MB (edge intermediate)
__device__ __half g_W12h[CC * CC];                 // W1@W2, n-major, fp16
__device__ float  g_bvec[CC];                      // b1@W2

__device__ int   g_off_e[EE + 1], g_off_n[NN + 1];
__device__ int   g_adj_e[NNZ];   // grouped by dst(edge), values = src(node)
__device__ int   g_adj_n[NNZ];   // grouped by src(node), values = dst(edge)
__device__ float g_binv[EE], g_dinv[NN];

// ---------------- fused setup: degrees + scan + CSR fill (one block) -------
__global__ __launch_bounds__(1024) void setup_kernel(const int* __restrict__ hidx) {
    __shared__ int se[EE];      // edge degree -> cursor
    __shared__ int sn[NN];      // node degree -> cursor
    __shared__ int ssum[1024];
    const int t = threadIdx.x;

    for (int i = t; i < EE; i += 1024) se[i] = 0;
    for (int i = t; i < NN; i += 1024) sn[i] = 0;
    __syncthreads();
    for (int i = t; i < NNZ; i += 1024) {
        atomicAdd(&sn[hidx[i]], 1);
        atomicAdd(&se[hidx[NNZ + i]], 1);
    }
    __syncthreads();

    // scan edge degrees
    {
        int d0 = se[t*4], d1 = se[t*4+1], d2 = se[t*4+2], d3 = se[t*4+3];
        int s = d0 + d1 + d2 + d3;
        ssum[t] = s;
        __syncthreads();
        for (int o = 1; o < 1024; o <<= 1) {
            int v = (t >= o) ? ssum[t - o] : 0;
            __syncthreads();
            ssum[t] += v;
            __syncthreads();
        }
        int base = ssum[t] - s;
        int p0 = base, p1 = p0 + d0, p2 = p1 + d1, p3 = p2 + d2;
        g_off_e[t*4] = p0; g_off_e[t*4+1] = p1; g_off_e[t*4+2] = p2; g_off_e[t*4+3] = p3;
        g_binv[t*4]   = d0 > 0 ? 1.f / d0 : 0.f;
        g_binv[t*4+1] = d1 > 0 ? 1.f / d1 : 0.f;
        g_binv[t*4+2] = d2 > 0 ? 1.f / d2 : 0.f;
        g_binv[t*4+3] = d3 > 0 ? 1.f / d3 : 0.f;
        if (t == 1023) g_off_e[4096] = p3 + d3;
        se[t*4] = p0; se[t*4+1] = p1; se[t*4+2] = p2; se[t*4+3] = p3;
    }
    __syncthreads();
    // scan node degrees
    {
        int d0 = sn[t*4], d1 = sn[t*4+1], d2 = sn[t*4+2], d3 = sn[t*4+3];
        int s = d0 + d1 + d2 + d3;
        ssum[t] = s;
        __syncthreads();
        for (int o = 1; o < 1024; o <<= 1) {
            int v = (t >= o) ? ssum[t - o] : 0;
            __syncthreads();
            ssum[t] += v;
            __syncthreads();
        }
        int base = ssum[t] - s;
        int p0 = base, p1 = p0 + d0, p2 = p1 + d1, p3 = p2 + d2;
        g_off_n[t*4] = p0; g_off_n[t*4+1] = p1; g_off_n[t*4+2] = p2; g_off_n[t*4+3] = p3;
        g_dinv[t*4]   = d0 > 0 ? 1.f / d0 : 0.f;
        g_dinv[t*4+1] = d1 > 0 ? 1.f / d1 : 0.f;
        g_dinv[t*4+2] = d2 > 0 ? 1.f / d2 : 0.f;
        g_dinv[t*4+3] = d3 > 0 ? 1.f / d3 : 0.f;
        if (t == 1023) g_off_n[4096] = p3 + d3;
        sn[t*4] = p0; sn[t*4+1] = p1; sn[t*4+2] = p2; sn[t*4+3] = p3;
    }
    __syncthreads();
    // fill CSRs
    for (int i = t; i < NNZ; i += 1024) {
        int s_ = hidx[i], d_ = hidx[NNZ + i];
        int p = atomicAdd(&se[d_], 1);
        g_adj_e[p] = s_;
        int q = atomicAdd(&sn[s_], 1);
        g_adj_n[q] = d_;
    }
}

// X fp32 -> g_ahf fp16 (8 elements per thread)
__global__ __launch_bounds__(256) void conv_kernel(const float* __restrict__ x) {
    size_t id = (size_t)blockIdx.x * 256 + threadIdx.x;
    const float4* x4 = (const float4*)x;
    float4 a = x4[id * 2 + 0];
    float4 b = x4[id * 2 + 1];
    __half2 p0 = __floats2half2_rn(a.x, a.y);
    __half2 p1 = __floats2half2_rn(a.z, a.w);
    __half2 p2 = __floats2half2_rn(b.x, b.y);
    __half2 p3 = __floats2half2_rn(b.z, b.w);
    uint4 o;
    o.x = *(uint32_t*)&p0; o.y = *(uint32_t*)&p1;
    o.z = *(uint32_t*)&p2; o.w = *(uint32_t*)&p3;
    ((uint4*)g_ahf)[id] = o;
}

// W12 = W1 @ W2 (stored n-major fp16) ; bvec = b1 @ W2.
__global__ void w12_kernel(const float* __restrict__ W1,
                           const float* __restrict__ b1,
                           const float* __restrict__ W2) {
    __shared__ float row[CC];
    int j = threadIdx.x;
    int i = blockIdx.x;
    if (i < CC) {
        row[j] = W1[i * CC + j];
        __syncthreads();
        float acc = 0.0f;
#pragma unroll 8
        for (int k = 0; k < CC; k++) acc += row[k] * W2[k * CC + j];
        g_W12h[j * CC + i] = __float2half_rn(acc);   // n-major: [n=j][k=i]
    } else {
        row[j] = b1[j];
        __syncthreads();
        float acc = 0.0f;
#pragma unroll 8
        for (int k = 0; k < CC; k++) acc += row[k] * W2[k * CC + j];
        g_bvec[j] = acc;
    }
}

// ---------------- fp16 aggregation (one S half-step) ----------------
// One block: segment g x 8 batches. 32 lanes x uint4 (8 fp16 ch) cover C=256.
// Batch slab = 4096 rows * 32 uint4 = 2^17 uint4.
__device__ __forceinline__ void add8(float* a, uint4 v) {
    float2 f0 = __half22float2(*reinterpret_cast<__half2*>(&v.x));
    float2 f1 = __half22float2(*reinterpret_cast<__half2*>(&v.y));
    float2 f2 = __half22float2(*reinterpret_cast<__half2*>(&v.z));
    float2 f3 = __half22float2(*reinterpret_cast<__half2*>(&v.w));
    a[0] += f0.x; a[1] += f0.y; a[2] += f1.x; a[3] += f1.y;
    a[4] += f2.x; a[5] += f2.y; a[6] += f3.x; a[7] += f3.y;
}

__global__ __launch_bounds__(256) void agg_hf(int in_sel, int out_sel,
                                              int use_edge_csr) {
    const int* off   = use_edge_csr ? g_off_e : g_off_n;
    const int* adj   = use_edge_csr ? g_adj_e : g_adj_n;
    const float* inv = use_edge_csr ? g_binv  : g_dinv;
    const __half* in = (in_sel == 1) ? g_ahf : g_ehf;

    const int g    = blockIdx.x;
    const int lane = threadIdx.x & 31;
    const int bsub = threadIdx.x >> 5;
    const int b    = (blockIdx.y << 3) + bsub;

    const int s = off[g];
    const int e = off[g + 1];

    const uint4* in4 = (const uint4*)in + ((size_t)b << 17) + lane;

    float a0[8], a1[8];
#pragma unroll
    for (int i = 0; i < 8; i++) { a0[i] = 0.f; a1[i] = 0.f; }

    int j = s;
    for (; j + 4 <= e; j += 4) {
        uint4 v0 = in4[(size_t)adj[j + 0] * 32];
        uint4 v1 = in4[(size_t)adj[j + 1] * 32];
        uint4 v2 = in4[(size_t)adj[j + 2] * 32];
        uint4 v3 = in4[(size_t)adj[j + 3] * 32];
        add8(a0, v0); add8(a1, v1); add8(a0, v2); add8(a1, v3);
    }
    for (; j < e; j++) {
        uint4 v = in4[(size_t)adj[j] * 32];
        add8(a0, v);
    }

    const float sc = inv[g];
#pragma unroll
    for (int i = 0; i < 8; i++) a0[i] = (a0[i] + a1[i]) * sc;

    __half* outp = (out_sel == 1) ? g_ahf : g_ehf;
    __half2 q0 = __floats2half2_rn(a0[0], a0[1]);
    __half2 q1 = __floats2half2_rn(a0[2], a0[3]);
    __half2 q2 = __floats2half2_rn(a0[4], a0[5]);
    __half2 q3 = __floats2half2_rn(a0[6], a0[7]);
    uint4 o;
    o.x = *(uint32_t*)&q0; o.y = *(uint32_t*)&q1;
    o.z = *(uint32_t*)&q2; o.w = *(uint32_t*)&q3;
    ((uint4*)outp)[((size_t)b << 17) + (size_t)g * 32 + lane] = o;
}

// ---------------- fused pass4 + GEMM ----------------
// Block = 128 output rows (one batch) x all 256 cols.
// Phase 1: gather Z2 tile from g_ehf (node CSR) -> smem As (fp16, pitch 264)
// Phase 2: load whole W12 -> Bs (pitch 264)
// Phase 3: m16n8k16 mma loop; epilogue adds u*bvec + b2.
// Dyn smem: As 128*264 + Bs 256*264 halfs = 202752 B.
#define PITCH 264
#define AS_HALFS (128 * PITCH)
#define SMEM_BYTES ((AS_HALFS + 256 * PITCH) * 2)

__device__ __forceinline__ void ldm_x4(uint32_t& r0, uint32_t& r1,
                                       uint32_t& r2, uint32_t& r3, uint32_t addr) {
    asm volatile("ldmatrix.sync.aligned.m8n8.x4.shared.b16 {%0,%1,%2,%3}, [%4];"
                 : "=r"(r0), "=r"(r1), "=r"(r2), "=r"(r3) : "r"(addr));
}

__device__ __forceinline__ void mma_f16(float4& c,
                                        uint32_t a0, uint32_t a1, uint32_t a2, uint32_t a3,
                                        uint32_t b0, uint32_t b1) {
    asm volatile("mma.sync.aligned.m16n8k16.row.col.f32.f16.f16.f32 "
        "{%0,%1,%2,%3}, {%4,%5,%6,%7}, {%8,%9}, {%0,%1,%2,%3};"
        : "+f"(c.x), "+f"(c.y), "+f"(c.z), "+f"(c.w)
        : "r"(a0), "r"(a1), "r"(a2), "r"(a3), "r"(b0), "r"(b1));
}

__global__ __launch_bounds__(512) void gemm_fused(float* __restrict__ C,
                                                  const float* __restrict__ b2) {
    extern __shared__ __align__(16) __half smem[];
    __half* As = smem;
    __half* Bs = smem + AS_HALFS;

    const int tid  = threadIdx.x;
    const int wid  = tid >> 5;      // 16 warps
    const int lane = tid & 31;
    const int m0   = blockIdx.x * 128;
    const int b    = m0 >> 12;       // batch (constant per block)
    const int n0   = m0 & (NN - 1);  // node base

    // ---- Phase 1: gather 128 Z2 rows (warp w -> rows it*16 + w) ----
    {
        const uint4* in4 = (const uint4*)g_ehf + ((size_t)b << 17) + lane;
#pragma unroll
        for (int it = 0; it < 8; it++) {
            int r = it * 16 + wid;
            int n = n0 + r;
            int s = g_off_n[n];
            int e = g_off_n[n + 1];
            float a0[8], a1[8];
#pragma unroll
            for (int i = 0; i < 8; i++) { a0[i] = 0.f; a1[i] = 0.f; }
            int j = s;
            for (; j + 2 <= e; j += 2) {
                uint4 v0 = in4[(size_t)g_adj_n[j] * 32];
                uint4 v1 = in4[(size_t)g_adj_n[j + 1] * 32];
                add8(a0, v0); add8(a1, v1);
            }
            for (; j < e; j++) add8(a0, in4[(size_t)g_adj_n[j] * 32]);
            const float sc = g_dinv[n];
#pragma unroll
            for (int i = 0; i < 8; i++) a0[i] = (a0[i] + a1[i]) * sc;
            __half2 q0 = __floats2half2_rn(a0[0], a0[1]);
            __half2 q1 = __floats2half2_rn(a0[2], a0[3]);
            __half2 q2 = __floats2half2_rn(a0[4], a0[5]);
            __half2 q3 = __floats2half2_rn(a0[6], a0[7]);
            uint4 o;
            o.x = *(uint32_t*)&q0; o.y = *(uint32_t*)&q1;
            o.z = *(uint32_t*)&q2; o.w = *(uint32_t*)&q3;
            *(uint4*)&As[r * PITCH + lane * 8] = o;
        }
    }
    // ---- Phase 2: load whole W12 (n-major 256x256) into Bs ----
    {
        const uint4* B4 = (const uint4*)g_W12h;   // 32 uint4 per row
#pragma unroll
        for (int i = 0; i < 16; i++) {
            int id = i * 512 + tid;
            int row = id >> 5, c = id & 31;
            *(uint4*)&Bs[row * PITCH + c * 8] = B4[row * 32 + c];
        }
    }
    __syncthreads();

    // ---- Phase 3: mma loop ----
    const int g_   = lane >> 2;
    const int t    = lane & 3;
    const int wm   = wid & 3;       // 4 warps along M (32 rows each)
    const int wn   = wid >> 2;      // 4 warps along N (64 cols each)

    const uint32_t sA = (uint32_t)__cvta_generic_to_shared(As);
    const uint32_t sB = (uint32_t)__cvta_generic_to_shared(Bs);
    const int a_row = (lane & 7) + ((lane >> 3) & 1) * 8;
    const int a_k   = (lane >> 4) * 8;
    const int b_row = (lane & 7) + (lane >> 4) * 8;
    const int b_k   = ((lane >> 3) & 1) * 8;

    float4 acc[2][8];
#pragma unroll
    for (int mt = 0; mt < 2; mt++)
#pragma unroll
        for (int nt = 0; nt < 8; nt++) acc[mt][nt] = make_float4(0.f, 0.f, 0.f, 0.f);

#pragma unroll
    for (int kk = 0; kk < 16; kk++) {
        uint32_t af[2][4];
#pragma unroll
        for (int mt = 0; mt < 2; mt++) {
            int r = wm * 32 + mt * 16 + a_row;
            uint32_t addr = sA + (uint32_t)(r * PITCH + kk * 16 + a_k) * 2;
            ldm_x4(af[mt][0], af[mt][1], af[mt][2], af[mt][3], addr);
        }
        uint32_t bf[8][2];
#pragma unroll
        for (int np = 0; np < 4; np++) {
            int rr = wn * 64 + np * 16 + b_row;
            uint32_t addr = sB + (uint32_t)(rr * PITCH + kk * 16 + b_k) * 2;
            uint32_t r0, r1, r2, r3;
            ldm_x4(r0, r1, r2, r3, addr);
            bf[np * 2 + 0][0] = r0; bf[np * 2 + 0][1] = r1;
            bf[np * 2 + 1][0] = r2; bf[np * 2 + 1][1] = r3;
        }
#pragma unroll
        for (int mt = 0; mt < 2; mt++)
#pragma unroll
            for (int nt = 0; nt < 8; nt++)
                mma_f16(acc[mt][nt], af[mt][0], af[mt][1], af[mt][2], af[mt][3],
                        bf[nt][0], bf[nt][1]);
    }

    // epilogue: c += u(row)*bvec[col] + b2[col]
#pragma unroll
    for (int mt = 0; mt < 2; mt++) {
        int r = m0 + wm * 32 + mt * 16 + g_;
        float u0 = (g_dinv[r & (NN - 1)] > 0.f) ? 1.f : 0.f;
        float u1 = (g_dinv[(r + 8) & (NN - 1)] > 0.f) ? 1.f : 0.f;
#pragma unroll
        for (int nt = 0; nt < 8; nt++) {
            int col = wn * 64 + nt * 8 + 2 * t;
            float bv0 = g_bvec[col], bv1 = g_bvec[col + 1];
            float c0 = b2[col], c1 = b2[col + 1];
            float2 lo = make_float2(acc[mt][nt].x + u0 * bv0 + c0,
                                    acc[mt][nt].y + u0 * bv1 + c1);
            float2 hi = make_float2(acc[mt][nt].z + u1 * bv0 + c0,
                                    acc[mt][nt].w + u1 * bv1 + c1);
            *(float2*)&C[(size_t)r * CC + col] = lo;
            *(float2*)&C[(size_t)(r + 8) * CC + col] = hi;
        }
    }
}

// ---------------- launch ----------------
extern "C" void kernel_launch(void* const* d_in, const int* in_sizes, int n_in,
                              void* d_out, int out_size) {
    const float* x    = (const float*)d_in[0];
    const int*   hidx = (const int*)d_in[1];   // [2, NNZ]: row0 src, row1 dst
    const float* W1   = (const float*)d_in[2];
    const float* b1   = (const float*)d_in[3];
    const float* W2   = (const float*)d_in[4];
    const float* b2   = (const float*)d_in[5];
    float* out = (float*)d_out;

    static int smem_set = 0;
    if (!smem_set) {
        cudaFuncSetAttribute(gemm_fused, cudaFuncAttributeMaxDynamicSharedMemorySize,
                             SMEM_BYTES);
        smem_set = 1;
    }

    setup_kernel<<<1, 1024>>>(hidx);
    w12_kernel<<<CC + 1, 256>>>(W1, b1, W2);
    conv_kernel<<<(BB * NN * CC) / (256 * 8), 256>>>(x);

    // S application #1: X_h(g_ahf) -> g_ehf -> Z1(g_ahf)
    agg_hf<<<dim3(EE, BB / 8), 256>>>(1, 2, 1);
    agg_hf<<<dim3(NN, BB / 8), 256>>>(2, 1, 0);
    // S application #2 first half: Z1(g_ahf) -> g_ehf
    agg_hf<<<dim3(EE, BB / 8), 256>>>(1, 2, 1);

    // fused: Z2 = Dinv * H g_ehf ; out = Z2 @ W12 + u*bvec + b2
    gemm_fused<<<(BB * NN) / 128, 512, SMEM_BYTES>>>(out, b2);
}

// round 13
// speedup vs baseline: 1.0723x; 1.0723x over previous
#include <cuda_runtime.h>
#include <cuda_fp16.h>
#include <cstdint>

// Problem constants
#define BB   64
#define NN   4096
#define EE   4096
#define NNZ  32768
#define CC   256

// ---------------- static device scratch (no allocs allowed) ----------------
__device__ __half g_ahf[(size_t)BB * NN * CC];     // 134 MB (X_h / Z1 / Z2)
__device__ __half g_ehf[(size_t)BB * EE * CC];     // 134 MB (edge intermediate)
__device__ __half g_W12h[CC * CC];                 // W1@W2, n-major, fp16
__device__ float  g_bvec[CC];                      // b1@W2

__device__ int   g_off_e[EE + 1], g_off_n[NN + 1];
__device__ int   g_adj_e[NNZ];   // grouped by dst(edge), values = src(node)
__device__ int   g_adj_n[NNZ];   // grouped by src(node), values = dst(edge)
__device__ float g_binv[EE], g_dinv[NN];

// ---------------- fused setup: degrees + scan + CSR fill (one block) -------
__global__ __launch_bounds__(1024) void setup_kernel(const int* __restrict__ hidx) {
    __shared__ int se[EE];      // edge degree -> cursor
    __shared__ int sn[NN];      // node degree -> cursor
    __shared__ int ssum[1024];
    const int t = threadIdx.x;

    for (int i = t; i < EE; i += 1024) se[i] = 0;
    for (int i = t; i < NN; i += 1024) sn[i] = 0;
    __syncthreads();
    for (int i = t; i < NNZ; i += 1024) {
        atomicAdd(&sn[hidx[i]], 1);
        atomicAdd(&se[hidx[NNZ + i]], 1);
    }
    __syncthreads();

    // scan edge degrees
    {
        int d0 = se[t*4], d1 = se[t*4+1], d2 = se[t*4+2], d3 = se[t*4+3];
        int s = d0 + d1 + d2 + d3;
        ssum[t] = s;
        __syncthreads();
        for (int o = 1; o < 1024; o <<= 1) {
            int v = (t >= o) ? ssum[t - o] : 0;
            __syncthreads();
            ssum[t] += v;
            __syncthreads();
        }
        int base = ssum[t] - s;
        int p0 = base, p1 = p0 + d0, p2 = p1 + d1, p3 = p2 + d2;
        g_off_e[t*4] = p0; g_off_e[t*4+1] = p1; g_off_e[t*4+2] = p2; g_off_e[t*4+3] = p3;
        g_binv[t*4]   = d0 > 0 ? 1.f / d0 : 0.f;
        g_binv[t*4+1] = d1 > 0 ? 1.f / d1 : 0.f;
        g_binv[t*4+2] = d2 > 0 ? 1.f / d2 : 0.f;
        g_binv[t*4+3] = d3 > 0 ? 1.f / d3 : 0.f;
        if (t == 1023) g_off_e[4096] = p3 + d3;
        se[t*4] = p0; se[t*4+1] = p1; se[t*4+2] = p2; se[t*4+3] = p3;
    }
    __syncthreads();
    // scan node degrees
    {
        int d0 = sn[t*4], d1 = sn[t*4+1], d2 = sn[t*4+2], d3 = sn[t*4+3];
        int s = d0 + d1 + d2 + d3;
        ssum[t] = s;
        __syncthreads();
        for (int o = 1; o < 1024; o <<= 1) {
            int v = (t >= o) ? ssum[t - o] : 0;
            __syncthreads();
            ssum[t] += v;
            __syncthreads();
        }
        int base = ssum[t] - s;
        int p0 = base, p1 = p0 + d0, p2 = p1 + d1, p3 = p2 + d2;
        g_off_n[t*4] = p0; g_off_n[t*4+1] = p1; g_off_n[t*4+2] = p2; g_off_n[t*4+3] = p3;
        g_dinv[t*4]   = d0 > 0 ? 1.f / d0 : 0.f;
        g_dinv[t*4+1] = d1 > 0 ? 1.f / d1 : 0.f;
        g_dinv[t*4+2] = d2 > 0 ? 1.f / d2 : 0.f;
        g_dinv[t*4+3] = d3 > 0 ? 1.f / d3 : 0.f;
        if (t == 1023) g_off_n[4096] = p3 + d3;
        sn[t*4] = p0; sn[t*4+1] = p1; sn[t*4+2] = p2; sn[t*4+3] = p3;
    }
    __syncthreads();
    // fill CSRs
    for (int i = t; i < NNZ; i += 1024) {
        int s_ = hidx[i], d_ = hidx[NNZ + i];
        int p = atomicAdd(&se[d_], 1);
        g_adj_e[p] = s_;
        int q = atomicAdd(&sn[s_], 1);
        g_adj_n[q] = d_;
    }
}

// X fp32 -> g_ahf fp16 (8 elements per thread)
__global__ __launch_bounds__(256) void conv_kernel(const float* __restrict__ x) {
    size_t id = (size_t)blockIdx.x * 256 + threadIdx.x;
    const float4* x4 = (const float4*)x;
    float4 a = x4[id * 2 + 0];
    float4 b = x4[id * 2 + 1];
    __half2 p0 = __floats2half2_rn(a.x, a.y);
    __half2 p1 = __floats2half2_rn(a.z, a.w);
    __half2 p2 = __floats2half2_rn(b.x, b.y);
    __half2 p3 = __floats2half2_rn(b.z, b.w);
    uint4 o;
    o.x = *(uint32_t*)&p0; o.y = *(uint32_t*)&p1;
    o.z = *(uint32_t*)&p2; o.w = *(uint32_t*)&p3;
    ((uint4*)g_ahf)[id] = o;
}

// W12 = W1 @ W2 (stored n-major fp16) ; bvec = b1 @ W2.
__global__ void w12_kernel(const float* __restrict__ W1,
                           const float* __restrict__ b1,
                           const float* __restrict__ W2) {
    __shared__ float row[CC];
    int j = threadIdx.x;
    int i = blockIdx.x;
    if (i < CC) {
        row[j] = W1[i * CC + j];
        __syncthreads();
        float acc = 0.0f;
#pragma unroll 8
        for (int k = 0; k < CC; k++) acc += row[k] * W2[k * CC + j];
        g_W12h[j * CC + i] = __float2half_rn(acc);   // n-major: [n=j][k=i]
    } else {
        row[j] = b1[j];
        __syncthreads();
        float acc = 0.0f;
#pragma unroll 8
        for (int k = 0; k < CC; k++) acc += row[k] * W2[k * CC + j];
        g_bvec[j] = acc;
    }
}

// ---------------- fp16 aggregation (one S half-step) ----------------
// One block: segment g x 8 batches. 32 lanes x uint4 (8 fp16 ch) cover C=256.
// Batch slab = 4096 rows * 32 uint4 = 2^17 uint4.
__device__ __forceinline__ void add8(float* a, uint4 v) {
    float2 f0 = __half22float2(*reinterpret_cast<__half2*>(&v.x));
    float2 f1 = __half22float2(*reinterpret_cast<__half2*>(&v.y));
    float2 f2 = __half22float2(*reinterpret_cast<__half2*>(&v.z));
    float2 f3 = __half22float2(*reinterpret_cast<__half2*>(&v.w));
    a[0] += f0.x; a[1] += f0.y; a[2] += f1.x; a[3] += f1.y;
    a[4] += f2.x; a[5] += f2.y; a[6] += f3.x; a[7] += f3.y;
}

// pairwise: s = v0 + v1 in fp16 (HADD2 x4), then widen+accumulate once
__device__ __forceinline__ void addp(float* a, uint4 v0, uint4 v1) {
    __half2 s0 = __hadd2(*reinterpret_cast<__half2*>(&v0.x),
                         *reinterpret_cast<__half2*>(&v1.x));
    __half2 s1 = __hadd2(*reinterpret_cast<__half2*>(&v0.y),
                         *reinterpret_cast<__half2*>(&v1.y));
    __half2 s2 = __hadd2(*reinterpret_cast<__half2*>(&v0.z),
                         *reinterpret_cast<__half2*>(&v1.z));
    __half2 s3 = __hadd2(*reinterpret_cast<__half2*>(&v0.w),
                         *reinterpret_cast<__half2*>(&v1.w));
    float2 f0 = __half22float2(s0);
    float2 f1 = __half22float2(s1);
    float2 f2 = __half22float2(s2);
    float2 f3 = __half22float2(s3);
    a[0] += f0.x; a[1] += f0.y; a[2] += f1.x; a[3] += f1.y;
    a[4] += f2.x; a[5] += f2.y; a[6] += f3.x; a[7] += f3.y;
}

__global__ __launch_bounds__(256) void agg_hf(int in_sel, int out_sel,
                                              int use_edge_csr) {
    const int* off   = use_edge_csr ? g_off_e : g_off_n;
    const int* adj   = use_edge_csr ? g_adj_e : g_adj_n;
    const float* inv = use_edge_csr ? g_binv  : g_dinv;
    const __half* in = (in_sel == 1) ? g_ahf : g_ehf;

    const int g    = blockIdx.x;
    const int lane = threadIdx.x & 31;
    const int bsub = threadIdx.x >> 5;
    const int b    = (blockIdx.y << 3) + bsub;

    const int s = off[g];
    const int e = off[g + 1];

    const uint4* in4 = (const uint4*)in + ((size_t)b << 17) + lane;

    float a0[8], a1[8];
#pragma unroll
    for (int i = 0; i < 8; i++) { a0[i] = 0.f; a1[i] = 0.f; }

    int j = s;
    for (; j + 4 <= e; j += 4) {
        uint4 v0 = in4[(size_t)adj[j + 0] * 32];
        uint4 v1 = in4[(size_t)adj[j + 1] * 32];
        uint4 v2 = in4[(size_t)adj[j + 2] * 32];
        uint4 v3 = in4[(size_t)adj[j + 3] * 32];
        addp(a0, v0, v1);
        addp(a1, v2, v3);
    }
    if (j + 2 <= e) {
        uint4 v0 = in4[(size_t)adj[j + 0] * 32];
        uint4 v1 = in4[(size_t)adj[j + 1] * 32];
        addp(a0, v0, v1);
        j += 2;
    }
    if (j < e) {
        uint4 v = in4[(size_t)adj[j] * 32];
        add8(a0, v);
    }

    const float sc = inv[g];
#pragma unroll
    for (int i = 0; i < 8; i++) a0[i] = (a0[i] + a1[i]) * sc;

    __half* outp = (out_sel == 1) ? g_ahf : g_ehf;
    __half2 q0 = __floats2half2_rn(a0[0], a0[1]);
    __half2 q1 = __floats2half2_rn(a0[2], a0[3]);
    __half2 q2 = __floats2half2_rn(a0[4], a0[5]);
    __half2 q3 = __floats2half2_rn(a0[6], a0[7]);
    uint4 o;
    o.x = *(uint32_t*)&q0; o.y = *(uint32_t*)&q1;
    o.z = *(uint32_t*)&q2; o.w = *(uint32_t*)&q3;
    ((uint4*)outp)[((size_t)b << 17) + (size_t)g * 32 + lane] = o;
}

// ---------------- fp16 tensor-core GEMM: out = Z2 @ W12 + u*bvec + b2 ----
// A = g_ahf [M,256] fp16 row-major; B = g_W12h [n][k] fp16.
// BM=128, BN=128, BK=32, 256 threads (8 warps: 4 m x 2 n), warp tile 32x64.
// mma.m16n8k16, fragments via ldmatrix.x4 on padded smem (40 halfs/row).
#define APAD 40

__device__ __forceinline__ void ldm_x4(uint32_t& r0, uint32_t& r1,
                                       uint32_t& r2, uint32_t& r3, uint32_t addr) {
    asm volatile("ldmatrix.sync.aligned.m8n8.x4.shared.b16 {%0,%1,%2,%3}, [%4];"
                 : "=r"(r0), "=r"(r1), "=r"(r2), "=r"(r3) : "r"(addr));
}

__device__ __forceinline__ void mma_f16(float4& c,
                                        uint32_t a0, uint32_t a1, uint32_t a2, uint32_t a3,
                                        uint32_t b0, uint32_t b1) {
    asm volatile("mma.sync.aligned.m16n8k16.row.col.f32.f16.f16.f32 "
        "{%0,%1,%2,%3}, {%4,%5,%6,%7}, {%8,%9}, {%0,%1,%2,%3};"
        : "+f"(c.x), "+f"(c.y), "+f"(c.z), "+f"(c.w)
        : "r"(a0), "r"(a1), "r"(a2), "r"(a3), "r"(b0), "r"(b1));
}

__global__ __launch_bounds__(256) void gemm_hf(float* __restrict__ C,
                                               const float* __restrict__ b2) {
    __shared__ __align__(16) __half As[128 * APAD];
    __shared__ __align__(16) __half Bs[128 * APAD];

    const int tid  = threadIdx.x;
    const int wid  = tid >> 5;
    const int lane = tid & 31;
    const int g    = lane >> 2;
    const int t    = lane & 3;
    const int wm   = wid & 3;      // 4 warps along M (32 rows each)
    const int wn   = wid >> 2;     // 2 warps along N (64 cols each)
    const int m0   = blockIdx.x * 128;
    const int n0   = blockIdx.y * 128;

    float4 acc[2][8];
#pragma unroll
    for (int mt = 0; mt < 2; mt++)
#pragma unroll
        for (int nt = 0; nt < 8; nt++) acc[mt][nt] = make_float4(0.f, 0.f, 0.f, 0.f);

    const uint4* A4 = (const uint4*)g_ahf;   // 32 uint4 per 256-half row
    const uint4* B4 = (const uint4*)g_W12h;

    const uint32_t sA = (uint32_t)__cvta_generic_to_shared(As);
    const uint32_t sB = (uint32_t)__cvta_generic_to_shared(Bs);
    const int a_row = (lane & 7) + ((lane >> 3) & 1) * 8;
    const int a_k   = (lane >> 4) * 8;
    const int b_row = (lane & 7) + (lane >> 4) * 8;
    const int b_k   = ((lane >> 3) & 1) * 8;

    uint4 ra[2], rb[2];
#pragma unroll
    for (int i = 0; i < 2; i++) {
        int id = i * 256 + tid;
        int row = id >> 2, c4 = id & 3;
        ra[i] = A4[(size_t)(m0 + row) * 32 + c4];
        rb[i] = B4[(size_t)(n0 + row) * 32 + c4];
    }

    for (int kc = 0; kc < 8; kc++) {
#pragma unroll
        for (int i = 0; i < 2; i++) {
            int id = i * 256 + tid;
            int row = id >> 2, c4 = id & 3;
            *(uint4*)&As[row * APAD + c4 * 8] = ra[i];
            *(uint4*)&Bs[row * APAD + c4 * 8] = rb[i];
        }
        __syncthreads();
        if (kc < 7) {
#pragma unroll
            for (int i = 0; i < 2; i++) {
                int id = i * 256 + tid;
                int row = id >> 2, c4 = id & 3;
                ra[i] = A4[(size_t)(m0 + row) * 32 + (kc + 1) * 4 + c4];
                rb[i] = B4[(size_t)(n0 + row) * 32 + (kc + 1) * 4 + c4];
            }
        }
#pragma unroll
        for (int ks = 0; ks < 2; ks++) {
            uint32_t af[2][4];
#pragma unroll
            for (int mt = 0; mt < 2; mt++) {
                int r = wm * 32 + mt * 16 + a_row;
                uint32_t addr = sA + (uint32_t)(r * APAD + ks * 16 + a_k) * 2;
                ldm_x4(af[mt][0], af[mt][1], af[mt][2], af[mt][3], addr);
            }
            uint32_t bf[8][2];
#pragma unroll
            for (int np = 0; np < 4; np++) {
                int r = wn * 64 + np * 16 + b_row;
                uint32_t addr = sB + (uint32_t)(r * APAD + ks * 16 + b_k) * 2;
                uint32_t r0, r1, r2, r3;
                ldm_x4(r0, r1, r2, r3, addr);
                bf[np * 2 + 0][0] = r0; bf[np * 2 + 0][1] = r1;
                bf[np * 2 + 1][0] = r2; bf[np * 2 + 1][1] = r3;
            }
#pragma unroll
            for (int mt = 0; mt < 2; mt++)
#pragma unroll
                for (int nt = 0; nt < 8; nt++)
                    mma_f16(acc[mt][nt], af[mt][0], af[mt][1], af[mt][2], af[mt][3],
                            bf[nt][0], bf[nt][1]);
        }
        __syncthreads();
    }

    // epilogue: c += u(row)*bvec[col] + b2[col]
#pragma unroll
    for (int mt = 0; mt < 2; mt++) {
        int r = m0 + wm * 32 + mt * 16 + g;
        float u0 = (g_dinv[r & (NN - 1)] > 0.f) ? 1.f : 0.f;
        float u1 = (g_dinv[(r + 8) & (NN - 1)] > 0.f) ? 1.f : 0.f;
#pragma unroll
        for (int nt = 0; nt < 8; nt++) {
            int col = n0 + wn * 64 + nt * 8 + 2 * t;
            float bv0 = g_bvec[col], bv1 = g_bvec[col + 1];
            float c0 = b2[col], c1 = b2[col + 1];
            float2 lo = make_float2(acc[mt][nt].x + u0 * bv0 + c0,
                                    acc[mt][nt].y + u0 * bv1 + c1);
            float2 hi = make_float2(acc[mt][nt].z + u1 * bv0 + c0,
                                    acc[mt][nt].w + u1 * bv1 + c1);
            *(float2*)&C[(size_t)r * CC + col] = lo;
            *(float2*)&C[(size_t)(r + 8) * CC + col] = hi;
        }
    }
}

// ---------------- launch ----------------
extern "C" void kernel_launch(void* const* d_in, const int* in_sizes, int n_in,
                              void* d_out, int out_size) {
    const float* x    = (const float*)d_in[0];
    const int*   hidx = (const int*)d_in[1];   // [2, NNZ]: row0 src, row1 dst
    const float* W1   = (const float*)d_in[2];
    const float* b1   = (const float*)d_in[3];
    const float* W2   = (const float*)d_in[4];
    const float* b2   = (const float*)d_in[5];
    float* out = (float*)d_out;

    setup_kernel<<<1, 1024>>>(hidx);
    w12_kernel<<<CC + 1, 256>>>(W1, b1, W2);
    conv_kernel<<<(BB * NN * CC) / (256 * 8), 256>>>(x);

    // S application #1: X_h(g_ahf) -> g_ehf -> Z1(g_ahf)
    agg_hf<<<dim3(EE, BB / 8), 256>>>(1, 2, 1);
    agg_hf<<<dim3(NN, BB / 8), 256>>>(2, 1, 0);
    // S application #2: Z1(g_ahf) -> g_ehf -> Z2(g_ahf)
    agg_hf<<<dim3(EE, BB / 8), 256>>>(1, 2, 1);
    agg_hf<<<dim3(NN, BB / 8), 256>>>(2, 1, 0);

    // out = Z2 @ W12 + u*bvec + b2   (fp16 mma, fp32 accum)
    gemm_hf<<<dim3((BB * NN) / 128, CC / 128), 256>>>(out, b2);
}

// round 15
// speedup vs baseline: 1.2233x; 1.1408x over previous
#include <cuda_runtime.h>
#include <cuda_fp16.h>
#include <cstdint>

// Problem constants
#define BB   64
#define NN   4096
#define EE   4096
#define NNZ  32768
#define CC   256

// ---------------- static device scratch (no allocs allowed) ----------------
__device__ __half g_ahf[(size_t)BB * NN * CC];     // 134 MB (X_h / Z1 / Z2)
__device__ __half g_ehf[(size_t)BB * EE * CC];     // 134 MB (edge intermediate)
__device__ __half g_W12h[CC * CC];                 // W1@W2, n-major, fp16
__device__ float  g_bvec[CC];                      // b1@W2

__device__ int   g_off_e[EE + 1], g_off_n[NN + 1];
__device__ int   g_adj_e[NNZ];   // grouped by dst(edge), values = src(node)
__device__ int   g_adj_n[NNZ];   // grouped by src(node), values = dst(edge)
__device__ float g_binv[EE], g_dinv[NN];

// ---------------- fused setup: degrees + scan + CSR fill (one block) -------
__global__ __launch_bounds__(1024) void setup_kernel(const int* __restrict__ hidx) {
    __shared__ int se[EE];      // edge degree -> cursor
    __shared__ int sn[NN];      // node degree -> cursor
    __shared__ int ssum[1024];
    const int t = threadIdx.x;

    for (int i = t; i < EE; i += 1024) se[i] = 0;
    for (int i = t; i < NN; i += 1024) sn[i] = 0;
    __syncthreads();
    for (int i = t; i < NNZ; i += 1024) {
        atomicAdd(&sn[hidx[i]], 1);
        atomicAdd(&se[hidx[NNZ + i]], 1);
    }
    __syncthreads();

    // scan edge degrees
    {
        int d0 = se[t*4], d1 = se[t*4+1], d2 = se[t*4+2], d3 = se[t*4+3];
        int s = d0 + d1 + d2 + d3;
        ssum[t] = s;
        __syncthreads();
        for (int o = 1; o < 1024; o <<= 1) {
            int v = (t >= o) ? ssum[t - o] : 0;
            __syncthreads();
            ssum[t] += v;
            __syncthreads();
        }
        int base = ssum[t] - s;
        int p0 = base, p1 = p0 + d0, p2 = p1 + d1, p3 = p2 + d2;
        g_off_e[t*4] = p0; g_off_e[t*4+1] = p1; g_off_e[t*4+2] = p2; g_off_e[t*4+3] = p3;
        g_binv[t*4]   = d0 > 0 ? 1.f / d0 : 0.f;
        g_binv[t*4+1] = d1 > 0 ? 1.f / d1 : 0.f;
        g_binv[t*4+2] = d2 > 0 ? 1.f / d2 : 0.f;
        g_binv[t*4+3] = d3 > 0 ? 1.f / d3 : 0.f;
        if (t == 1023) g_off_e[4096] = p3 + d3;
        se[t*4] = p0; se[t*4+1] = p1; se[t*4+2] = p2; se[t*4+3] = p3;
    }
    __syncthreads();
    // scan node degrees
    {
        int d0 = sn[t*4], d1 = sn[t*4+1], d2 = sn[t*4+2], d3 = sn[t*4+3];
        int s = d0 + d1 + d2 + d3;
        ssum[t] = s;
        __syncthreads();
        for (int o = 1; o < 1024; o <<= 1) {
            int v = (t >= o) ? ssum[t - o] : 0;
            __syncthreads();
            ssum[t] += v;
            __syncthreads();
        }
        int base = ssum[t] - s;
        int p0 = base, p1 = p0 + d0, p2 = p1 + d1, p3 = p2 + d2;
        g_off_n[t*4] = p0; g_off_n[t*4+1] = p1; g_off_n[t*4+2] = p2; g_off_n[t*4+3] = p3;
        g_dinv[t*4]   = d0 > 0 ? 1.f / d0 : 0.f;
        g_dinv[t*4+1] = d1 > 0 ? 1.f / d1 : 0.f;
        g_dinv[t*4+2] = d2 > 0 ? 1.f / d2 : 0.f;
        g_dinv[t*4+3] = d3 > 0 ? 1.f / d3 : 0.f;
        if (t == 1023) g_off_n[4096] = p3 + d3;
        sn[t*4] = p0; sn[t*4+1] = p1; sn[t*4+2] = p2; sn[t*4+3] = p3;
    }
    __syncthreads();
    // fill CSRs
    for (int i = t; i < NNZ; i += 1024) {
        int s_ = hidx[i], d_ = hidx[NNZ + i];
        int p = atomicAdd(&se[d_], 1);
        g_adj_e[p] = s_;
        int q = atomicAdd(&sn[s_], 1);
        g_adj_n[q] = d_;
    }
}

// X fp32 -> g_ahf fp16 (8 elements per thread)
__global__ __launch_bounds__(256) void conv_kernel(const float* __restrict__ x) {
    size_t id = (size_t)blockIdx.x * 256 + threadIdx.x;
    const float4* x4 = (const float4*)x;
    float4 a = x4[id * 2 + 0];
    float4 b = x4[id * 2 + 1];
    __half2 p0 = __floats2half2_rn(a.x, a.y);
    __half2 p1 = __floats2half2_rn(a.z, a.w);
    __half2 p2 = __floats2half2_rn(b.x, b.y);
    __half2 p3 = __floats2half2_rn(b.z, b.w);
    uint4 o;
    o.x = *(uint32_t*)&p0; o.y = *(uint32_t*)&p1;
    o.z = *(uint32_t*)&p2; o.w = *(uint32_t*)&p3;
    ((uint4*)g_ahf)[id] = o;
}

// W12 = W1 @ W2 (stored n-major fp16) ; bvec = b1 @ W2.
__global__ void w12_kernel(const float* __restrict__ W1,
                           const float* __restrict__ b1,
                           const float* __restrict__ W2) {
    __shared__ float row[CC];
    int j = threadIdx.x;
    int i = blockIdx.x;
    if (i < CC) {
        row[j] = W1[i * CC + j];
        __syncthreads();
        float acc = 0.0f;
#pragma unroll 8
        for (int k = 0; k < CC; k++) acc += row[k] * W2[k * CC + j];
        g_W12h[j * CC + i] = __float2half_rn(acc);   // n-major: [n=j][k=i]
    } else {
        row[j] = b1[j];
        __syncthreads();
        float acc = 0.0f;
#pragma unroll 8
        for (int k = 0; k < CC; k++) acc += row[k] * W2[k * CC + j];
        g_bvec[j] = acc;
    }
}

// ---------------- fp16 aggregation (one S half-step) ----------------
// One block: segment g x 8 batches. 32 lanes x uint4 (8 fp16 ch) cover C=256.
// Batch slab = 2^17 uint4; all indices fit in 32 bits (max 2^23).
__device__ __forceinline__ __half2 h2(uint32_t u) {
    return *reinterpret_cast<__half2*>(&u);
}

__device__ __forceinline__ void acc8(float* a, __half2 tx, __half2 ty,
                                     __half2 tz, __half2 tw) {
    float2 f0 = __half22float2(tx);
    float2 f1 = __half22float2(ty);
    float2 f2 = __half22float2(tz);
    float2 f3 = __half22float2(tw);
    a[0] += f0.x; a[1] += f0.y; a[2] += f1.x; a[3] += f1.y;
    a[4] += f2.x; a[5] += f2.y; a[6] += f3.x; a[7] += f3.y;
}

// 4-neighbor fp16 tree (12 HADD2), single widen + fp32 accumulate
__device__ __forceinline__ void addq(float* a, uint4 v0, uint4 v1,
                                     uint4 v2, uint4 v3) {
    __half2 tx = __hadd2(__hadd2(h2(v0.x), h2(v1.x)), __hadd2(h2(v2.x), h2(v3.x)));
    __half2 ty = __hadd2(__hadd2(h2(v0.y), h2(v1.y)), __hadd2(h2(v2.y), h2(v3.y)));
    __half2 tz = __hadd2(__hadd2(h2(v0.z), h2(v1.z)), __hadd2(h2(v2.z), h2(v3.z)));
    __half2 tw = __hadd2(__hadd2(h2(v0.w), h2(v1.w)), __hadd2(h2(v2.w), h2(v3.w)));
    acc8(a, tx, ty, tz, tw);
}

// 2-neighbor fp16 pair (4 HADD2), widen + accumulate
__device__ __forceinline__ void addp(float* a, uint4 v0, uint4 v1) {
    acc8(a, __hadd2(h2(v0.x), h2(v1.x)), __hadd2(h2(v0.y), h2(v1.y)),
            __hadd2(h2(v0.z), h2(v1.z)), __hadd2(h2(v0.w), h2(v1.w)));
}

__device__ __forceinline__ void add8(float* a, uint4 v) {
    acc8(a, h2(v.x), h2(v.y), h2(v.z), h2(v.w));
}

__global__ __launch_bounds__(256) void agg_hf(int in_sel, int out_sel,
                                              int use_edge_csr) {
    const int* off   = use_edge_csr ? g_off_e : g_off_n;
    const int* adj   = use_edge_csr ? g_adj_e : g_adj_n;
    const float* inv = use_edge_csr ? g_binv  : g_dinv;
    const __half* in = (in_sel == 1) ? g_ahf : g_ehf;

    const int g    = blockIdx.x;
    const int lane = threadIdx.x & 31;
    const int bsub = threadIdx.x >> 5;
    const int b    = (blockIdx.y << 3) + bsub;

    const int s = off[g];
    const int e = off[g + 1];

    // 32-bit indexing: lane base within this batch slab
    const uint4* base4 = (const uint4*)in;
    const uint32_t lanep = ((uint32_t)b << 17) + (uint32_t)lane;

    float a0[8];
#pragma unroll
    for (int i = 0; i < 8; i++) a0[i] = 0.f;

    int j = s;
    for (; j + 4 <= e; j += 4) {
        uint32_t o0 = (uint32_t)adj[j + 0] << 5;
        uint32_t o1 = (uint32_t)adj[j + 1] << 5;
        uint32_t o2 = (uint32_t)adj[j + 2] << 5;
        uint32_t o3 = (uint32_t)adj[j + 3] << 5;
        uint4 v0 = base4[lanep + o0];
        uint4 v1 = base4[lanep + o1];
        uint4 v2 = base4[lanep + o2];
        uint4 v3 = base4[lanep + o3];
        addq(a0, v0, v1, v2, v3);
    }
    if (j + 2 <= e) {
        uint4 v0 = base4[lanep + ((uint32_t)adj[j + 0] << 5)];
        uint4 v1 = base4[lanep + ((uint32_t)adj[j + 1] << 5)];
        addp(a0, v0, v1);
        j += 2;
    }
    if (j < e) {
        add8(a0, base4[lanep + ((uint32_t)adj[j] << 5)]);
    }

    const float sc = inv[g];
#pragma unroll
    for (int i = 0; i < 8; i++) a0[i] *= sc;

    __half* outp = (out_sel == 1) ? g_ahf : g_ehf;
    __half2 q0 = __floats2half2_rn(a0[0], a0[1]);
    __half2 q1 = __floats2half2_rn(a0[2], a0[3]);
    __half2 q2 = __floats2half2_rn(a0[4], a0[5]);
    __half2 q3 = __floats2half2_rn(a0[6], a0[7]);
    uint4 o;
    o.x = *(uint32_t*)&q0; o.y = *(uint32_t*)&q1;
    o.z = *(uint32_t*)&q2; o.w = *(uint32_t*)&q3;
    ((uint4*)outp)[lanep + ((uint32_t)g << 5)] = o;
}

// ---------------- fp16 tensor-core GEMM: out = Z2 @ W12 + u*bvec + b2 ----
// A = g_ahf [M,256] fp16 row-major; B = g_W12h [n][k] fp16.
// BM=128, BN=128, BK=32, 256 threads (8 warps: 4 m x 2 n), warp tile 32x64.
#define APAD 40

__device__ __forceinline__ void ldm_x4(uint32_t& r0, uint32_t& r1,
                                       uint32_t& r2, uint32_t& r3, uint32_t addr) {
    asm volatile("ldmatrix.sync.aligned.m8n8.x4.shared.b16 {%0,%1,%2,%3}, [%4];"
                 : "=r"(r0), "=r"(r1), "=r"(r2), "=r"(r3) : "r"(addr));
}

__device__ __forceinline__ void mma_f16(float4& c,
                                        uint32_t a0, uint32_t a1, uint32_t a2, uint32_t a3,
                                        uint32_t b0, uint32_t b1) {
    asm volatile("mma.sync.aligned.m16n8k16.row.col.f32.f16.f16.f32 "
        "{%0,%1,%2,%3}, {%4,%5,%6,%7}, {%8,%9}, {%0,%1,%2,%3};"
        : "+f"(c.x), "+f"(c.y), "+f"(c.z), "+f"(c.w)
        : "r"(a0), "r"(a1), "r"(a2), "r"(a3), "r"(b0), "r"(b1));
}

__global__ __launch_bounds__(256) void gemm_hf(float* __restrict__ C,
                                               const float* __restrict__ b2) {
    __shared__ __align__(16) __half As[128 * APAD];
    __shared__ __align__(16) __half Bs[128 * APAD];

    const int tid  = threadIdx.x;
    const int wid  = tid >> 5;
    const int lane = tid & 31;
    const int g    = lane >> 2;
    const int t    = lane & 3;
    const int wm   = wid & 3;      // 4 warps along M (32 rows each)
    const int wn   = wid >> 2;     // 2 warps along N (64 cols each)
    const int m0   = blockIdx.x * 128;
    const int n0   = blockIdx.y * 128;

    float4 acc[2][8];
#pragma unroll
    for (int mt = 0; mt < 2; mt++)
#pragma unroll
        for (int nt = 0; nt < 8; nt++) acc[mt][nt] = make_float4(0.f, 0.f, 0.f, 0.f);

    const uint4* A4 = (const uint4*)g_ahf;   // 32 uint4 per 256-half row
    const uint4* B4 = (const uint4*)g_W12h;

    const uint32_t sA = (uint32_t)__cvta_generic_to_shared(As);
    const uint32_t sB = (uint32_t)__cvta_generic_to_shared(Bs);
    const int a_row = (lane & 7) + ((lane >> 3) & 1) * 8;
    const int a_k   = (lane >> 4) * 8;
    const int b_row = (lane & 7) + (lane >> 4) * 8;
    const int b_k   = ((lane >> 3) & 1) * 8;

    uint4 ra[2], rb[2];
#pragma unroll
    for (int i = 0; i < 2; i++) {
        int id = i * 256 + tid;
        int row = id >> 2, c4 = id & 3;
        ra[i] = A4[(size_t)(m0 + row) * 32 + c4];
        rb[i] = B4[(size_t)(n0 + row) * 32 + c4];
    }

    for (int kc = 0; kc < 8; kc++) {
#pragma unroll
        for (int i = 0; i < 2; i++) {
            int id = i * 256 + tid;
            int row = id >> 2, c4 = id & 3;
            *(uint4*)&As[row * APAD + c4 * 8] = ra[i];
            *(uint4*)&Bs[row * APAD + c4 * 8] = rb[i];
        }
        __syncthreads();
        if (kc < 7) {
#pragma unroll
            for (int i = 0; i < 2; i++) {
                int id = i * 256 + tid;
                int row = id >> 2, c4 = id & 3;
                ra[i] = A4[(size_t)(m0 + row) * 32 + (kc + 1) * 4 + c4];
                rb[i] = B4[(size_t)(n0 + row) * 32 + (kc + 1) * 4 + c4];
            }
        }
#pragma unroll
        for (int ks = 0; ks < 2; ks++) {
            uint32_t af[2][4];
#pragma unroll
            for (int mt = 0; mt < 2; mt++) {
                int r = wm * 32 + mt * 16 + a_row;
                uint32_t addr = sA + (uint32_t)(r * APAD + ks * 16 + a_k) * 2;
                ldm_x4(af[mt][0], af[mt][1], af[mt][2], af[mt][3], addr);
            }
            uint32_t bf[8][2];
#pragma unroll
            for (int np = 0; np < 4; np++) {
                int r = wn * 64 + np * 16 + b_row;
                uint32_t addr = sB + (uint32_t)(r * APAD + ks * 16 + b_k) * 2;
                uint32_t r0, r1, r2, r3;
                ldm_x4(r0, r1, r2, r3, addr);
                bf[np * 2 + 0][0] = r0; bf[np * 2 + 0][1] = r1;
                bf[np * 2 + 1][0] = r2; bf[np * 2 + 1][1] = r3;
            }
#pragma unroll
            for (int mt = 0; mt < 2; mt++)
#pragma unroll
                for (int nt = 0; nt < 8; nt++)
                    mma_f16(acc[mt][nt], af[mt][0], af[mt][1], af[mt][2], af[mt][3],
                            bf[nt][0], bf[nt][1]);
        }
        __syncthreads();
    }

    // epilogue: c += u(row)*bvec[col] + b2[col]
#pragma unroll
    for (int mt = 0; mt < 2; mt++) {
        int r = m0 + wm * 32 + mt * 16 + g;
        float u0 = (g_dinv[r & (NN - 1)] > 0.f) ? 1.f : 0.f;
        float u1 = (g_dinv[(r + 8) & (NN - 1)] > 0.f) ? 1.f : 0.f;
#pragma unroll
        for (int nt = 0; nt < 8; nt++) {
            int col = n0 + wn * 64 + nt * 8 + 2 * t;
            float bv0 = g_bvec[col], bv1 = g_bvec[col + 1];
            float c0 = b2[col], c1 = b2[col + 1];
            float2 lo = make_float2(acc[mt][nt].x + u0 * bv0 + c0,
                                    acc[mt][nt].y + u0 * bv1 + c1);
            float2 hi = make_float2(acc[mt][nt].z + u1 * bv0 + c0,
                                    acc[mt][nt].w + u1 * bv1 + c1);
            *(float2*)&C[(size_t)r * CC + col] = lo;
            *(float2*)&C[(size_t)(r + 8) * CC + col] = hi;
        }
    }
}

// ---------------- launch ----------------
extern "C" void kernel_launch(void* const* d_in, const int* in_sizes, int n_in,
                              void* d_out, int out_size) {
    const float* x    = (const float*)d_in[0];
    const int*   hidx = (const int*)d_in[1];   // [2, NNZ]: row0 src, row1 dst
    const float* W1   = (const float*)d_in[2];
    const float* b1   = (const float*)d_in[3];
    const float* W2   = (const float*)d_in[4];
    const float* b2   = (const float*)d_in[5];
    float* out = (float*)d_out;

    setup_kernel<<<1, 1024>>>(hidx);
    w12_kernel<<<CC + 1, 256>>>(W1, b1, W2);
    conv_kernel<<<(BB * NN * CC) / (256 * 8), 256>>>(x);

    // S application #1: X_h(g_ahf) -> g_ehf -> Z1(g_ahf)
    agg_hf<<<dim3(EE, BB / 8), 256>>>(1, 2, 1);
    agg_hf<<<dim3(NN, BB / 8), 256>>>(2, 1, 0);
    // S application #2: Z1(g_ahf) -> g_ehf -> Z2(g_ahf)
    agg_hf<<<dim3(EE, BB / 8), 256>>>(1, 2, 1);
    agg_hf<<<dim3(NN, BB / 8), 256>>>(2, 1, 0);

    // out = Z2 @ W12 + u*bvec + b2   (fp16 mma, fp32 accum)
    gemm_hf<<<dim3((BB * NN) / 128, CC / 128), 256>>>(out, b2);
}